// round 1
// baseline (speedup 1.0000x reference)
#include <cuda_runtime.h>
#include <math.h>

// ---------------- problem constants ----------------
#define BATCH 32
#define HQ    32
#define KVH   8
#define GQ    4           // HQ / KVH
#define D_HEAD 128
#define HID   4096
#define QKV_COLS 6144     // (HQ + 2*KVH) * D_HEAD
#define WIN   4096
#define NSPLIT 16
#define PAIRS (BATCH*KVH) // 256

// ---------------- device scratch (no allocations allowed) ----------------
__device__ float g_XT  [HID * BATCH];           // x transposed: [k][m]
__device__ float g_xqkv[BATCH * QKV_COLS];      // raw qkv gemm output
__device__ float g_q   [BATCH * HQ  * D_HEAD];  // rope'd q  [b][h][d]
__device__ float g_k   [BATCH * KVH * D_HEAD];  // rope'd new k [b][kv][d]
__device__ float g_v   [BATCH * KVH * D_HEAD];  // new v
__device__ float g_ctxT[HID * BATCH];           // ctx transposed: [c][m]
__device__ float g_pm  [PAIRS * NSPLIT * GQ];
__device__ float g_pl  [PAIRS * NSPLIT * GQ];
__device__ float g_pa  [PAIRS * NSPLIT * GQ * D_HEAD];

// ---------------- 1) transpose x (32x4096 -> 4096x32) ----------------
__global__ void k_transpose(const float* __restrict__ x) {
    int i = blockIdx.x * blockDim.x + threadIdx.x;   // 131072 threads
    int k = i >> 5, m = i & 31;
    g_XT[i] = x[m * HID + k];
}

// ---------------- 2) skinny GEMM:  Y[32][NCOL] = X[32][4096] @ W[4096][NCOL]
// X given transposed as XT[k][m]. In-CTA K-split by 16 slices, 16 cols/CTA.
__global__ void __launch_bounds__(256) k_gemm32(int which,
                                                const float* __restrict__ W,
                                                float* __restrict__ Yext,
                                                int NCOL) {
    __shared__ float xs[16 * 16 * 32];  // [slice][kk][m], 32 KB (reused as red buf)
    const float* __restrict__ XT = (which == 0) ? g_XT : g_ctxT;
    float* __restrict__ Y        = (which == 0) ? g_xqkv : Yext;

    const int tid   = threadIdx.x;
    const int c     = tid & 15;
    const int slice = tid >> 4;                 // 0..15
    const int col   = blockIdx.x * 16 + c;

    float acc[32];
#pragma unroll
    for (int m = 0; m < 32; ++m) acc[m] = 0.f;

    for (int stage = 0; stage < 16; ++stage) {
        __syncthreads();
        // cooperative load of 16 slices x 16 kk x 32 m = 8192 floats (coalesced)
#pragma unroll
        for (int it = 0; it < 8; ++it) {
            int j   = tid + it * 256;       // float4 index
            int flt = j << 2;
            int s   = flt >> 9;             // 512 floats per slice block
            int rem = flt & 511;
            int kg  = s * 256 + stage * 16 + (rem >> 5);
            ((float4*)xs)[j] = *(const float4*)&XT[kg * 32 + (rem & 31)];
        }
        __syncthreads();

        const float* wb = W + (slice * 256 + stage * 16) * NCOL + col;
#pragma unroll
        for (int kk = 0; kk < 16; ++kk) {
            float w = wb[kk * NCOL];
            const float4* xv = (const float4*)(xs + (slice * 16 + kk) * 32);
#pragma unroll
            for (int mv = 0; mv < 8; ++mv) {
                float4 xm = xv[mv];
                acc[4 * mv + 0] += xm.x * w;
                acc[4 * mv + 1] += xm.y * w;
                acc[4 * mv + 2] += xm.z * w;
                acc[4 * mv + 3] += xm.w * w;
            }
        }
    }

    // reduce the 16 K-slices through shared memory
    __syncthreads();
    float* red = xs;   // [32][256]
#pragma unroll
    for (int m = 0; m < 32; ++m) red[m * 256 + tid] = acc[m];
    __syncthreads();
#pragma unroll
    for (int it = 0; it < 2; ++it) {
        int o  = tid + it * 256;           // 512 outputs: (m, c2)
        int m  = o >> 4;
        int c2 = o & 15;
        float s = 0.f;
#pragma unroll
        for (int sl = 0; sl < 16; ++sl) s += red[m * 256 + sl * 16 + c2];
        Y[m * NCOL + blockIdx.x * 16 + c2] = s;
    }
}

// ---------------- 3) RoPE + split into q/k/v ----------------
__global__ void k_rope(const float* __restrict__ cosc,
                       const float* __restrict__ sinc,
                       const int* __restrict__ sp_p) {
    int i = blockIdx.x * blockDim.x + threadIdx.x;   // 32*6144 threads
    int m = i / QKV_COLS;
    int c = i - m * QKV_COLS;
    int sp = *sp_p;
    float v = g_xqkv[i];
    if (c < HQ * D_HEAD) {
        int d = c & 127;
        float cs = cosc[sp * D_HEAD + d], sn = sinc[sp * D_HEAD + d];
        int pc = (d < 64) ? (c + 64) : (c - 64);
        float o = g_xqkv[m * QKV_COLS + pc];
        float r = (d < 64) ? -o : o;
        g_q[m * (HQ * D_HEAD) + c] = v * cs + r * sn;
    } else if (c < (HQ + KVH) * D_HEAD) {
        int cc = c - HQ * D_HEAD;
        int d = cc & 127;
        float cs = cosc[sp * D_HEAD + d], sn = sinc[sp * D_HEAD + d];
        int pc = (d < 64) ? (c + 64) : (c - 64);
        float o = g_xqkv[m * QKV_COLS + pc];
        float r = (d < 64) ? -o : o;
        g_k[m * (KVH * D_HEAD) + cc] = v * cs + r * sn;
    } else {
        int cc = c - (HQ + KVH) * D_HEAD;
        g_v[m * (KVH * D_HEAD) + cc] = v;
    }
}

// ---------------- 4) flash-decode partials (split-KV) ----------------
__global__ void __launch_bounds__(128) k_attn_part(const float* __restrict__ CK,
                                                   const float* __restrict__ CV,
                                                   const int* __restrict__ sp_p,
                                                   const int* __restrict__ cp_p) {
    const int split = blockIdx.x;
    const int pair  = blockIdx.y;            // b*8 + kv
    const int b  = pair >> 3;
    const int kv = pair & 7;
    const int sp = *sp_p;
    const int cp = *cp_p;
    const int L  = sp + 1;                   // positions 0..sp are unmasked
    const int rows = (L + NSPLIT - 1) / NSPLIT;
    const int lo = split * rows;
    const int hi = min(lo + rows, L);
    const int tid = threadIdx.x, lane = tid & 31, wid = tid >> 5;

    float4 q[GQ];
#pragma unroll
    for (int g = 0; g < GQ; ++g)
        q[g] = *(const float4*)&g_q[((b * HQ) + kv * GQ + g) * D_HEAD + lane * 4];

    const float* Kb = CK + (size_t)pair * WIN * D_HEAD;
    const float* Vb = CV + (size_t)pair * WIN * D_HEAD;

    float m[GQ], l[GQ];
    float4 a[GQ];
#pragma unroll
    for (int g = 0; g < GQ; ++g) {
        m[g] = -1e30f; l[g] = 0.f;
        a[g].x = a[g].y = a[g].z = a[g].w = 0.f;
    }
    const float scale = 0.08838834764831845f;   // 1/sqrt(128)

    for (int r = lo + wid; r < hi; r += 4) {
        const float* kr = (r == cp) ? (g_k + pair * D_HEAD) : (Kb + (size_t)r * D_HEAD);
        const float* vr = (r == cp) ? (g_v + pair * D_HEAD) : (Vb + (size_t)r * D_HEAD);
        float4 kk = *(const float4*)(kr + lane * 4);
        float4 vv = *(const float4*)(vr + lane * 4);
#pragma unroll
        for (int g = 0; g < GQ; ++g) {
            float s = q[g].x * kk.x + q[g].y * kk.y + q[g].z * kk.z + q[g].w * kk.w;
            s += __shfl_xor_sync(0xffffffffu, s, 16);
            s += __shfl_xor_sync(0xffffffffu, s, 8);
            s += __shfl_xor_sync(0xffffffffu, s, 4);
            s += __shfl_xor_sync(0xffffffffu, s, 2);
            s += __shfl_xor_sync(0xffffffffu, s, 1);
            s *= scale;
            float mn   = fmaxf(m[g], s);
            float corr = __expf(m[g] - mn);
            float p    = __expf(s - mn);
            m[g] = mn;
            l[g] = l[g] * corr + p;
            a[g].x = a[g].x * corr + p * vv.x;
            a[g].y = a[g].y * corr + p * vv.y;
            a[g].z = a[g].z * corr + p * vv.z;
            a[g].w = a[g].w * corr + p * vv.w;
        }
    }

    // combine the 4 warps of this CTA
    __shared__ float smm[4][GQ], sml[4][GQ];
    __shared__ float sma[4][GQ][D_HEAD];
#pragma unroll
    for (int g = 0; g < GQ; ++g) {
        if (lane == 0) { smm[wid][g] = m[g]; sml[wid][g] = l[g]; }
        *(float4*)&sma[wid][g][lane * 4] = a[g];
    }
    __syncthreads();

    const int base = (pair * NSPLIT + split) * GQ;   // tid == d (0..127)
#pragma unroll
    for (int g = 0; g < GQ; ++g) {
        float M = fmaxf(fmaxf(smm[0][g], smm[1][g]), fmaxf(smm[2][g], smm[3][g]));
        float Z = 0.f, A = 0.f;
#pragma unroll
        for (int w = 0; w < 4; ++w) {
            float e = __expf(smm[w][g] - M);
            Z += e * sml[w][g];
            A += e * sma[w][g][tid];
        }
        g_pa[(base + g) * D_HEAD + tid] = A;
        if (tid == 0) { g_pm[base + g] = M; g_pl[base + g] = Z; }
    }
}

// ---------------- 5) combine splits -> ctx (transposed for the wo gemm) ----
__global__ void __launch_bounds__(128) k_attn_red() {
    const int pair = blockIdx.x;
    const int b = pair >> 3, kv = pair & 7;
    const int d = threadIdx.x;
#pragma unroll
    for (int g = 0; g < GQ; ++g) {
        float M = -1e30f;
        for (int s = 0; s < NSPLIT; ++s)
            M = fmaxf(M, g_pm[(pair * NSPLIT + s) * GQ + g]);
        float Z = 0.f, A = 0.f;
        for (int s = 0; s < NSPLIT; ++s) {
            int idx = (pair * NSPLIT + s) * GQ + g;
            float e = __expf(g_pm[idx] - M);
            Z += e * g_pl[idx];
            A += e * g_pa[idx * D_HEAD + d];
        }
        int c = (kv * GQ + g) * D_HEAD + d;     // column = h*128 + d
        g_ctxT[c * BATCH + b] = A / Z;
    }
}

// ---------------- launch ----------------
extern "C" void kernel_launch(void* const* d_in, const int* in_sizes, int n_in,
                              void* d_out, int out_size) {
    const float* x    = (const float*)d_in[0];
    const float* wqkv = (const float*)d_in[1];
    const float* wo   = (const float*)d_in[2];
    const float* ck   = (const float*)d_in[3];
    const float* cv   = (const float*)d_in[4];
    const float* cosc = (const float*)d_in[5];
    const float* sinc = (const float*)d_in[6];
    // d_in[7] = attn_mask: equivalent to (pos <= start_pos), applied analytically
    const int* sp = (const int*)d_in[8];
    const int* cp = (const int*)d_in[9];
    float* out = (float*)d_out;

    k_transpose<<<512, 256>>>(x);
    k_gemm32<<<QKV_COLS / 16, 256>>>(0, wqkv, nullptr, QKV_COLS);
    k_rope<<<(BATCH * QKV_COLS) / 256, 256>>>(cosc, sinc, sp);
    dim3 ag(NSPLIT, PAIRS);
    k_attn_part<<<ag, 128>>>(ck, cv, sp, cp);
    k_attn_red<<<PAIRS, 128>>>();
    k_gemm32<<<HID / 16, 256>>>(1, wo, out, HID);
}

// round 2
// speedup vs baseline: 1.0016x; 1.0016x over previous
#include <cuda_runtime.h>
#include <math.h>

// ---------------- problem constants ----------------
#define BATCH 32
#define HQ    32
#define KVH   8
#define GQ    4           // HQ / KVH
#define D_HEAD 128
#define HID   4096
#define QKV_COLS 6144     // (HQ + 2*KVH) * D_HEAD
#define WIN   4096
#define NSPLIT 16
#define PAIRS (BATCH*KVH) // 256

// ---------------- device scratch (no allocations allowed) ----------------
__device__ float g_XT  [HID * BATCH];           // x transposed: [k][m]
__device__ float g_xqkv[BATCH * QKV_COLS];      // raw qkv gemm output
__device__ float g_q   [BATCH * HQ  * D_HEAD];  // rope'd q  [b][h][d]
__device__ float g_k   [BATCH * KVH * D_HEAD];  // rope'd new k [b][kv][d]
__device__ float g_v   [BATCH * KVH * D_HEAD];  // new v
__device__ float g_ctxT[HID * BATCH];           // ctx transposed: [c][m]
__device__ float g_pm  [PAIRS * NSPLIT * GQ];
__device__ float g_pl  [PAIRS * NSPLIT * GQ];
__device__ float g_pa  [PAIRS * NSPLIT * GQ * D_HEAD];

// ---------------- 1) transpose x (32x4096 -> 4096x32) ----------------
__global__ void k_transpose(const float* __restrict__ x) {
    int i = blockIdx.x * blockDim.x + threadIdx.x;   // 131072 threads
    int k = i >> 5, m = i & 31;
    g_XT[i] = x[m * HID + k];
}

// ---------------- 2) skinny GEMM:  Y[32][NCOL] = X[32][4096] @ W[4096][NCOL]
// X given transposed as XT[k][m]. In-CTA K-split by 16 slices, 16 cols/CTA.
__global__ void __launch_bounds__(256) k_gemm32(int which,
                                                const float* __restrict__ W,
                                                float* __restrict__ Yext,
                                                int NCOL) {
    __shared__ float xs[16 * 16 * 32];  // [slice][kk][m], 32 KB (reused as red buf)
    const float* __restrict__ XT = (which == 0) ? g_XT : g_ctxT;
    float* __restrict__ Y        = (which == 0) ? g_xqkv : Yext;

    const int tid   = threadIdx.x;
    const int c     = tid & 15;
    const int slice = tid >> 4;                 // 0..15
    const int col   = blockIdx.x * 16 + c;

    float acc[32];
#pragma unroll
    for (int m = 0; m < 32; ++m) acc[m] = 0.f;

    for (int stage = 0; stage < 16; ++stage) {
        __syncthreads();
        // cooperative load of 16 slices x 16 kk x 32 m = 8192 floats (coalesced)
#pragma unroll
        for (int it = 0; it < 8; ++it) {
            int j   = tid + it * 256;       // float4 index
            int flt = j << 2;
            int s   = flt >> 9;             // 512 floats per slice block
            int rem = flt & 511;
            int kg  = s * 256 + stage * 16 + (rem >> 5);
            ((float4*)xs)[j] = *(const float4*)&XT[kg * 32 + (rem & 31)];
        }
        __syncthreads();

        const float* wb = W + (slice * 256 + stage * 16) * NCOL + col;
#pragma unroll
        for (int kk = 0; kk < 16; ++kk) {
            float w = wb[kk * NCOL];
            const float4* xv = (const float4*)(xs + (slice * 16 + kk) * 32);
#pragma unroll
            for (int mv = 0; mv < 8; ++mv) {
                float4 xm = xv[mv];
                acc[4 * mv + 0] += xm.x * w;
                acc[4 * mv + 1] += xm.y * w;
                acc[4 * mv + 2] += xm.z * w;
                acc[4 * mv + 3] += xm.w * w;
            }
        }
    }

    // reduce the 16 K-slices through shared memory
    __syncthreads();
    float* red = xs;   // [32][256]
#pragma unroll
    for (int m = 0; m < 32; ++m) red[m * 256 + tid] = acc[m];
    __syncthreads();
#pragma unroll
    for (int it = 0; it < 2; ++it) {
        int o  = tid + it * 256;           // 512 outputs: (m, c2)
        int m  = o >> 4;
        int c2 = o & 15;
        float s = 0.f;
#pragma unroll
        for (int sl = 0; sl < 16; ++sl) s += red[m * 256 + sl * 16 + c2];
        Y[m * NCOL + blockIdx.x * 16 + c2] = s;
    }
}

// ---------------- 3) RoPE + split into q/k/v ----------------
__global__ void k_rope(const float* __restrict__ cosc,
                       const float* __restrict__ sinc,
                       const int* __restrict__ sp_p) {
    int i = blockIdx.x * blockDim.x + threadIdx.x;   // 32*6144 threads
    int m = i / QKV_COLS;
    int c = i - m * QKV_COLS;
    int sp = *sp_p;
    float v = g_xqkv[i];
    if (c < HQ * D_HEAD) {
        int d = c & 127;
        float cs = cosc[sp * D_HEAD + d], sn = sinc[sp * D_HEAD + d];
        int pc = (d < 64) ? (c + 64) : (c - 64);
        float o = g_xqkv[m * QKV_COLS + pc];
        float r = (d < 64) ? -o : o;
        g_q[m * (HQ * D_HEAD) + c] = v * cs + r * sn;
    } else if (c < (HQ + KVH) * D_HEAD) {
        int cc = c - HQ * D_HEAD;
        int d = cc & 127;
        float cs = cosc[sp * D_HEAD + d], sn = sinc[sp * D_HEAD + d];
        int pc = (d < 64) ? (c + 64) : (c - 64);
        float o = g_xqkv[m * QKV_COLS + pc];
        float r = (d < 64) ? -o : o;
        g_k[m * (KVH * D_HEAD) + cc] = v * cs + r * sn;
    } else {
        int cc = c - (HQ + KVH) * D_HEAD;
        g_v[m * (KVH * D_HEAD) + cc] = v;
    }
}

// ---------------- 4) flash-decode partials (split-KV) ----------------
__global__ void __launch_bounds__(128) k_attn_part(const float* __restrict__ CK,
                                                   const float* __restrict__ CV,
                                                   const int* __restrict__ sp_p,
                                                   const int* __restrict__ cp_p) {
    const int split = blockIdx.x;
    const int pair  = blockIdx.y;            // b*8 + kv
    const int b  = pair >> 3;
    const int kv = pair & 7;
    const int sp = *sp_p;
    const int cp = *cp_p;
    const int L  = sp + 1;                   // positions 0..sp are unmasked
    const int rows = (L + NSPLIT - 1) / NSPLIT;
    const int lo = split * rows;
    const int hi = min(lo + rows, L);
    const int tid = threadIdx.x, lane = tid & 31, wid = tid >> 5;

    float4 q[GQ];
#pragma unroll
    for (int g = 0; g < GQ; ++g)
        q[g] = *(const float4*)&g_q[((b * HQ) + kv * GQ + g) * D_HEAD + lane * 4];

    const float* Kb = CK + (size_t)pair * WIN * D_HEAD;
    const float* Vb = CV + (size_t)pair * WIN * D_HEAD;

    float m[GQ], l[GQ];
    float4 a[GQ];
#pragma unroll
    for (int g = 0; g < GQ; ++g) {
        m[g] = -1e30f; l[g] = 0.f;
        a[g].x = a[g].y = a[g].z = a[g].w = 0.f;
    }
    const float scale = 0.08838834764831845f;   // 1/sqrt(128)

    for (int r = lo + wid; r < hi; r += 4) {
        const float* kr = (r == cp) ? (g_k + pair * D_HEAD) : (Kb + (size_t)r * D_HEAD);
        const float* vr = (r == cp) ? (g_v + pair * D_HEAD) : (Vb + (size_t)r * D_HEAD);
        float4 kk = *(const float4*)(kr + lane * 4);
        float4 vv = *(const float4*)(vr + lane * 4);
#pragma unroll
        for (int g = 0; g < GQ; ++g) {
            float s = q[g].x * kk.x + q[g].y * kk.y + q[g].z * kk.z + q[g].w * kk.w;
            s += __shfl_xor_sync(0xffffffffu, s, 16);
            s += __shfl_xor_sync(0xffffffffu, s, 8);
            s += __shfl_xor_sync(0xffffffffu, s, 4);
            s += __shfl_xor_sync(0xffffffffu, s, 2);
            s += __shfl_xor_sync(0xffffffffu, s, 1);
            s *= scale;
            float mn   = fmaxf(m[g], s);
            float corr = __expf(m[g] - mn);
            float p    = __expf(s - mn);
            m[g] = mn;
            l[g] = l[g] * corr + p;
            a[g].x = a[g].x * corr + p * vv.x;
            a[g].y = a[g].y * corr + p * vv.y;
            a[g].z = a[g].z * corr + p * vv.z;
            a[g].w = a[g].w * corr + p * vv.w;
        }
    }

    // combine the 4 warps of this CTA
    __shared__ float smm[4][GQ], sml[4][GQ];
    __shared__ float sma[4][GQ][D_HEAD];
#pragma unroll
    for (int g = 0; g < GQ; ++g) {
        if (lane == 0) { smm[wid][g] = m[g]; sml[wid][g] = l[g]; }
        *(float4*)&sma[wid][g][lane * 4] = a[g];
    }
    __syncthreads();

    const int base = (pair * NSPLIT + split) * GQ;   // tid == d (0..127)
#pragma unroll
    for (int g = 0; g < GQ; ++g) {
        float M = fmaxf(fmaxf(smm[0][g], smm[1][g]), fmaxf(smm[2][g], smm[3][g]));
        float Z = 0.f, A = 0.f;
#pragma unroll
        for (int w = 0; w < 4; ++w) {
            float e = __expf(smm[w][g] - M);
            Z += e * sml[w][g];
            A += e * sma[w][g][tid];
        }
        g_pa[(base + g) * D_HEAD + tid] = A;
        if (tid == 0) { g_pm[base + g] = M; g_pl[base + g] = Z; }
    }
}

// ---------------- 5) combine splits -> ctx (transposed for the wo gemm) ----
__global__ void __launch_bounds__(128) k_attn_red() {
    const int pair = blockIdx.x;
    const int b = pair >> 3, kv = pair & 7;
    const int d = threadIdx.x;
#pragma unroll
    for (int g = 0; g < GQ; ++g) {
        float M = -1e30f;
        for (int s = 0; s < NSPLIT; ++s)
            M = fmaxf(M, g_pm[(pair * NSPLIT + s) * GQ + g]);
        float Z = 0.f, A = 0.f;
        for (int s = 0; s < NSPLIT; ++s) {
            int idx = (pair * NSPLIT + s) * GQ + g;
            float e = __expf(g_pm[idx] - M);
            Z += e * g_pl[idx];
            A += e * g_pa[idx * D_HEAD + d];
        }
        int c = (kv * GQ + g) * D_HEAD + d;     // column = h*128 + d
        g_ctxT[c * BATCH + b] = A / Z;
    }
}

// ---------------- launch ----------------
extern "C" void kernel_launch(void* const* d_in, const int* in_sizes, int n_in,
                              void* d_out, int out_size) {
    const float* x    = (const float*)d_in[0];
    const float* wqkv = (const float*)d_in[1];
    const float* wo   = (const float*)d_in[2];
    const float* ck   = (const float*)d_in[3];
    const float* cv   = (const float*)d_in[4];
    const float* cosc = (const float*)d_in[5];
    const float* sinc = (const float*)d_in[6];
    // d_in[7] = attn_mask: equivalent to (pos <= start_pos), applied analytically
    const int* sp = (const int*)d_in[8];
    const int* cp = (const int*)d_in[9];
    float* out = (float*)d_out;

    k_transpose<<<512, 256>>>(x);
    k_gemm32<<<QKV_COLS / 16, 256>>>(0, wqkv, nullptr, QKV_COLS);
    k_rope<<<(BATCH * QKV_COLS) / 256, 256>>>(cosc, sinc, sp);
    dim3 ag(NSPLIT, PAIRS);
    k_attn_part<<<ag, 128>>>(ck, cv, sp, cp);
    k_attn_red<<<PAIRS, 128>>>();
    k_gemm32<<<HID / 16, 256>>>(1, wo, out, HID);
}